// round 15
// baseline (speedup 1.0000x reference)
#include <cuda_runtime.h>
#include <cuda_bf16.h>
#include <cstdint>

// ---------------- problem constants ----------------
#define B_    2
#define S_    2048
#define E_    2048
#define H_    16
#define HKV_  8
#define D_    64
#define M_    (B_ * S_)
#define LAMBDA_INIT_F 0.78360576653f
#define ONE_MINUS_LI  0.21639423347f
#define SCALE_F       0.125f

// ---------------- scratch (device globals) ----------------
__device__ float g_q[M_ * 2048];   // (B,S,2H,D) raw projection (pre-rope fp32)
__device__ float g_k[M_ * 1024];
__device__ float g_v[M_ * 1024];
__device__ float g_a[M_ * 2048];
__device__ float g_lam;
__device__ __nv_bfloat16 g_xh[M_ * 2048],    g_xl[M_ * 2048];
__device__ __nv_bfloat16 g_ah[M_ * 2048],    g_al[M_ * 2048];
__device__ __nv_bfloat16 g_wqh[2048 * 2048], g_wql[2048 * 2048];
__device__ __nv_bfloat16 g_wkh[1024 * 2048], g_wkl[1024 * 2048];
__device__ __nv_bfloat16 g_wvh[1024 * 2048], g_wvl[1024 * 2048];
__device__ __nv_bfloat16 g_woh[2048 * 2048], g_wol[2048 * 2048];
__device__ __nv_bfloat16 g_qh[M_ * 2048], g_ql[M_ * 2048];
__device__ __nv_bfloat16 g_kh[M_ * 1024], g_kl[M_ * 1024];
__device__ __nv_bfloat16 g_vth[M_ * 1024], g_vtl[M_ * 1024];  // (B,HKV,2D,S)

// ---------------- helpers ----------------
__device__ __forceinline__ uint32_t smem_u32(const void* p) {
    uint32_t a;
    asm("{ .reg .u64 t; cvta.to.shared.u64 t, %1; cvt.u32.u64 %0, t; }" : "=r"(a) : "l"(p));
    return a;
}
__device__ __forceinline__ void cvt_pair(float x, float y, uint32_t& hp, uint32_t& lp) {
    __nv_bfloat16 hx = __float2bfloat16_rn(x);
    __nv_bfloat16 hy = __float2bfloat16_rn(y);
    float lx = x - __bfloat162float(hx);
    float ly = y - __bfloat162float(hy);
    hp = ((uint32_t)__bfloat16_as_ushort(hy) << 16) | (uint32_t)__bfloat16_as_ushort(hx);
    __nv_bfloat162 l2 = __floats2bfloat162_rn(lx, ly);
    lp = *reinterpret_cast<uint32_t*>(&l2);
}

#define LDSM4(r, a) \
    asm volatile("ldmatrix.sync.aligned.m8n8.x4.shared.b16 {%0,%1,%2,%3}, [%4];" \
        : "=r"((r)[0]), "=r"((r)[1]), "=r"((r)[2]), "=r"((r)[3]) : "r"(a))

#define MMA16816(c, a, b) \
    asm volatile("mma.sync.aligned.m16n8k16.row.col.f32.bf16.bf16.f32 " \
        "{%0,%1,%2,%3}, {%4,%5,%6,%7}, {%8,%9}, {%0,%1,%2,%3};" \
        : "+f"((c)[0]), "+f"((c)[1]), "+f"((c)[2]), "+f"((c)[3]) \
        : "r"((a)[0]), "r"((a)[1]), "r"((a)[2]), "r"((a)[3]), "r"((b)[0]), "r"((b)[1]))

#define CP16(dst, src) \
    asm volatile("cp.async.cg.shared.global [%0], [%1], 16;" :: "r"(dst), "l"(src))
#define CP_COMMIT() asm volatile("cp.async.commit_group;" ::: "memory")
#define CP_WAIT1()  asm volatile("cp.async.wait_group 1;" ::: "memory")
#define CP_WAIT0()  asm volatile("cp.async.wait_group 0;" ::: "memory")

// ---------------- split kernel: fp32 -> bf16 hi + bf16 lo ----------------
__global__ void __launch_bounds__(256) cvt_split(const float* __restrict__ src,
                                                 __nv_bfloat16* __restrict__ hi,
                                                 __nv_bfloat16* __restrict__ lo, int n8) {
    int i = blockIdx.x * blockDim.x + threadIdx.x;
    if (i >= n8) return;
    const float4* s = (const float4*)src + (size_t)i * 2;
    float4 v0 = s[0], v1 = s[1];
    uint32_t h[4], l[4];
    cvt_pair(v0.x, v0.y, h[0], l[0]);
    cvt_pair(v0.z, v0.w, h[1], l[1]);
    cvt_pair(v1.x, v1.y, h[2], l[2]);
    cvt_pair(v1.z, v1.w, h[3], l[3]);
    *(uint4*)(hi + (size_t)i * 8) = make_uint4(h[0], h[1], h[2], h[3]);
    *(uint4*)(lo + (size_t)i * 8) = make_uint4(l[0], l[1], l[2], l[3]);
}

// ---------------- pure-bf16 HMMA GEMM, 256x256 tile, 512 thr, 2-stage cp.async -------
// warp grid 4x4, warp tile 64x64. Plane: 256 rows x 80 B. Stage = 4 planes = 80KB.
#define G3_PL    20480
#define G3_STAGE 81920
#define G3_SMEM  163840

__device__ __forceinline__ void g3_load(const __nv_bfloat16* __restrict__ Ah,
                                        const __nv_bfloat16* __restrict__ Al,
                                        const __nv_bfloat16* __restrict__ Wh,
                                        const __nv_bfloat16* __restrict__ Wl,
                                        int K, uint32_t sbase, int bm, int bn,
                                        int k0, int tid) {
#pragma unroll
    for (int i = 0; i < 2; i++) {
        int idx = tid + i * 512;
        int row = idx >> 2, j = idx & 3;
        uint32_t doff = (uint32_t)(row * 80 + j * 16);
        CP16(sbase + doff,              (Ah + (size_t)(bm + row) * K + k0 + j * 8));
        CP16(sbase + G3_PL + doff,      (Al + (size_t)(bm + row) * K + k0 + j * 8));
        CP16(sbase + 2 * G3_PL + doff,  (Wh + (size_t)(bn + row) * K + k0 + j * 8));
        CP16(sbase + 3 * G3_PL + doff,  (Wl + (size_t)(bn + row) * K + k0 + j * 8));
    }
}

__device__ __forceinline__ void gemm_big_body(
        const __nv_bfloat16* __restrict__ Ah, const __nv_bfloat16* __restrict__ Al,
        const __nv_bfloat16* __restrict__ Wh, const __nv_bfloat16* __restrict__ Wl,
        float* __restrict__ C, int N, int K, int bm, int bn) {
    extern __shared__ char smem[];
    const uint32_t sb0 = smem_u32(smem);
    const int tid = threadIdx.x, lane = tid & 31, wid = tid >> 5;
    const int wm = wid >> 2, wn = wid & 3;

    const uint32_t aoff = (uint32_t)((wm * 64 + ((lane >> 3) & 1) * 8 + (lane & 7)) * 80 +
                                     ((lane >> 4) & 1) * 16);
    const uint32_t boff = (uint32_t)((wn * 64 + ((lane >> 4) & 1) * 8 + (lane & 7)) * 80 +
                                     ((lane >> 3) & 1) * 16);

    float c[4][8][4];
#pragma unroll
    for (int i = 0; i < 4; i++)
#pragma unroll
        for (int j = 0; j < 8; j++)
#pragma unroll
            for (int q = 0; q < 4; q++) c[i][j][q] = 0.0f;

    const int nch = K >> 5;
    g3_load(Ah, Al, Wh, Wl, K, sb0, bm, bn, 0, tid);
    CP_COMMIT();
    g3_load(Ah, Al, Wh, Wl, K, sb0 + G3_STAGE, bm, bn, 32, tid);
    CP_COMMIT();

    int st = 0;
    for (int cidx = 0; cidx < nch; cidx++) {
        CP_WAIT1();
        __syncthreads();

        const uint32_t sA  = sb0 + st * G3_STAGE;
        const uint32_t sAl = sA + G3_PL;
        const uint32_t sW  = sA + 2 * G3_PL;
        const uint32_t sWl = sA + 3 * G3_PL;
#pragma unroll
        for (int ks = 0; ks < 2; ks++) {
            uint32_t bh[8][2], bl[8][2];
#pragma unroll
            for (int p = 0; p < 4; p++) {
                uint32_t r[4];
                LDSM4(r, sW + boff + p * 1280 + ks * 32);
                bh[2 * p][0] = r[0]; bh[2 * p][1] = r[1];
                bh[2 * p + 1][0] = r[2]; bh[2 * p + 1][1] = r[3];
                LDSM4(r, sWl + boff + p * 1280 + ks * 32);
                bl[2 * p][0] = r[0]; bl[2 * p][1] = r[1];
                bl[2 * p + 1][0] = r[2]; bl[2 * p + 1][1] = r[3];
            }
#pragma unroll
            for (int mt = 0; mt < 4; mt++) {
                uint32_t ah[4], al[4];
                LDSM4(ah, sA  + aoff + mt * 1280 + ks * 32);
                LDSM4(al, sAl + aoff + mt * 1280 + ks * 32);
#pragma unroll
                for (int nt = 0; nt < 8; nt++) {
                    MMA16816(c[mt][nt], ah, bh[nt]);
                    MMA16816(c[mt][nt], ah, bl[nt]);
                    MMA16816(c[mt][nt], al, bh[nt]);
                }
            }
        }
        __syncthreads();
        if (cidx + 2 < nch)
            g3_load(Ah, Al, Wh, Wl, K, sb0 + st * G3_STAGE, bm, bn, (cidx + 2) << 5, tid);
        CP_COMMIT();
        st ^= 1;
    }

    const int r0 = bm + wm * 64 + (lane >> 2);
    const int c0 = bn + wn * 64 + (lane & 3) * 2;
#pragma unroll
    for (int mt = 0; mt < 4; mt++)
#pragma unroll
        for (int nt = 0; nt < 8; nt++) {
            float* p0 = C + (size_t)(r0 + mt * 16) * N + c0 + nt * 8;
            float* p1 = p0 + 8 * N;
            *(float2*)p0 = make_float2(c[mt][nt][0], c[mt][nt][1]);
            *(float2*)p1 = make_float2(c[mt][nt][2], c[mt][nt][3]);
        }
}

__global__ void __launch_bounds__(512, 1)
gemm_big(const __nv_bfloat16* __restrict__ Ah, const __nv_bfloat16* __restrict__ Al,
         const __nv_bfloat16* __restrict__ Wh, const __nv_bfloat16* __restrict__ Wl,
         float* __restrict__ C, int N, int K) {
    gemm_big_body(Ah, Al, Wh, Wl, C, N, K, blockIdx.y * 256, blockIdx.x * 256);
}

// K and V projections merged into one full-wave launch (blockIdx.x selects W/C)
__global__ void __launch_bounds__(512, 1)
gemm_kv(const __nv_bfloat16* __restrict__ Ah, const __nv_bfloat16* __restrict__ Al,
        const __nv_bfloat16* __restrict__ Kh, const __nv_bfloat16* __restrict__ Kl,
        const __nv_bfloat16* __restrict__ Vh, const __nv_bfloat16* __restrict__ Vl,
        float* __restrict__ Ck, float* __restrict__ Cv, int K) {
    const int sel = blockIdx.x >> 2;
    const int bn = (blockIdx.x & 3) * 256;
    gemm_big_body(Ah, Al, sel ? Vh : Kh, sel ? Vl : Kl, sel ? Cv : Ck,
                  1024, K, blockIdx.y * 256, bn);
}

// ---------------- fast exp ----------------
__device__ __forceinline__ float fexp(float x) {
    x = fmaxf(x, -80.0f);
    float y  = x * 1.44269504088896f;
    float t  = y + 12582912.0f;
    int   e  = __float_as_int(t);
    float f  = y - (t - 12582912.0f);
    float p  = 1.33335581e-3f;
    p = fmaf(p, f, 9.61812911e-3f);
    p = fmaf(p, f, 5.55041087e-2f);
    p = fmaf(p, f, 2.40226507e-1f);
    p = fmaf(p, f, 6.93147181e-1f);
    p = fmaf(p, f, 1.0f);
    return __int_as_float(__float_as_int(p) + (e << 23));
}

// ---------------- prep: rope + hi/lo split for Q,K ----------------
#define QPAIRS (M_ * 32 * 32)
#define KPAIRS (M_ * 16 * 32)
__global__ void prep_qk(const float* __restrict__ cosb, const float* __restrict__ sinb) {
    int idx = blockIdx.x * blockDim.x + threadIdx.x;
    if (idx < QPAIRS) {
        int i = idx & 31;
        int head = (idx >> 5) & 31;
        int t = idx >> 10;
        int s = t & (S_ - 1);
        float c = cosb[s * 32 + i], sn = sinb[s * 32 + i];
        const float* p = g_q + (size_t)t * 2048 + head * 64 + 2 * i;
        float x1 = p[0], x2 = p[1];
        float o1 = x1 * c - x2 * sn;
        float o2 = x1 * sn + x2 * c;
        uint32_t hp, lp;
        cvt_pair(o1, o2, hp, lp);
        size_t off = (size_t)t * 2048 + head * 64 + 2 * i;
        *(uint32_t*)(g_qh + off) = hp;
        *(uint32_t*)(g_ql + off) = lp;
    } else if (idx < QPAIRS + KPAIRS) {
        int j = idx - QPAIRS;
        int i = j & 31;
        int head = (j >> 5) & 15;
        int t = j >> 9;
        int s = t & (S_ - 1);
        float c = cosb[s * 32 + i], sn = sinb[s * 32 + i];
        const float* p = g_k + (size_t)t * 1024 + head * 64 + 2 * i;
        float x1 = p[0], x2 = p[1];
        float o1 = x1 * c - x2 * sn;
        float o2 = x1 * sn + x2 * c;
        uint32_t hp, lp;
        cvt_pair(o1, o2, hp, lp);
        size_t off = (size_t)t * 1024 + head * 64 + 2 * i;
        *(uint32_t*)(g_kh + off) = hp;
        *(uint32_t*)(g_kl + off) = lp;
    }
}

// ---------------- prep: V transpose (dv-major) + hi/lo split ----------------
__global__ void __launch_bounds__(256) prep_vt() {
    __shared__ float vt[64][132];
    const int s0 = blockIdx.x * 64, kvh = blockIdx.y, b = blockIdx.z;
    const int tid = threadIdx.x;
#pragma unroll
    for (int i = 0; i < 8; i++) {
        int idx = tid + i * 256;
        int sl = idx >> 5, dv4 = (idx & 31) * 4;
        float4 v = *(const float4*)(g_v + (size_t)((b * S_ + s0 + sl) * 8 + kvh) * 128 + dv4);
        vt[sl][dv4] = v.x; vt[sl][dv4 + 1] = v.y; vt[sl][dv4 + 2] = v.z; vt[sl][dv4 + 3] = v.w;
    }
    __syncthreads();
    const int dv = tid >> 1, half = tid & 1;
    __nv_bfloat16* oh = g_vth + (size_t)((b * 8 + kvh) * 128 + dv) * 2048 + s0 + half * 32;
    __nv_bfloat16* ol = g_vtl + (size_t)((b * 8 + kvh) * 128 + dv) * 2048 + s0 + half * 32;
#pragma unroll
    for (int g = 0; g < 4; g++) {
        uint32_t hw[4], lw[4];
#pragma unroll
        for (int e = 0; e < 4; e++) {
            float f0 = vt[half * 32 + g * 8 + 2 * e][dv];
            float f1 = vt[half * 32 + g * 8 + 2 * e + 1][dv];
            cvt_pair(f0, f1, hw[e], lw[e]);
        }
        *(uint4*)(oh + g * 8) = make_uint4(hw[0], hw[1], hw[2], hw[3]);
        *(uint4*)(ol + g * 8) = make_uint4(lw[0], lw[1], lw[2], lw[3]);
    }
}

// ---------------- lambda scalar ----------------
__global__ void lam_kernel(const float* __restrict__ lq1, const float* __restrict__ lk1,
                           const float* __restrict__ lq2, const float* __restrict__ lk2) {
    __shared__ float s1a[2], s2a[2];
    int t = threadIdx.x;
    float p1 = lq1[t] * lk1[t];
    float p2 = lq2[t] * lk2[t];
#pragma unroll
    for (int o = 16; o > 0; o >>= 1) {
        p1 += __shfl_xor_sync(0xffffffffu, p1, o);
        p2 += __shfl_xor_sync(0xffffffffu, p2, o);
    }
    if ((t & 31) == 0) { s1a[t >> 5] = p1; s2a[t >> 5] = p2; }
    __syncthreads();
    if (t == 0)
        g_lam = expf(s1a[0] + s1a[1]) - expf(s2a[0] + s2a[1]) + LAMBDA_INIT_F;
}

// ---------------- HMMA dual-component flash attention, cp.async double-buffered ------
#define DA_KPL   9216
#define DA_KC    18432
#define DA_VPL   18432
#define DA_VOFF  36864
#define DA_STAGE 73728
#define DA_Q     147456
#define DA_SMEM  184320

__device__ __forceinline__ void da_load_tile(uint32_t stbase, int b, int kvh, int k0, int tid) {
#pragma unroll
    for (int i = 0; i < 8; i++) {
        int idx = tid + i * 256;
        int comp = idx >> 10, rem = idx & 1023;
        int plane = rem >> 9, r = (rem >> 3) & 63, j = idx & 7;
        const __nv_bfloat16* src = (plane ? g_kl : g_kh) +
            ((size_t)((b * S_ + k0 + r) * 16) + 2 * kvh + comp) * 64 + j * 8;
        CP16(stbase + comp * DA_KC + plane * DA_KPL + r * 144 + j * 16, src);
    }
#pragma unroll
    for (int i = 0; i < 8; i++) {
        int idx = tid + i * 256;
        int plane = idx >> 10, rem = idx & 1023;
        int dv = rem >> 3, j = idx & 7;
        const __nv_bfloat16* src = (plane ? g_vtl : g_vth) +
            (size_t)((b * 8 + kvh) * 128 + dv) * 2048 + k0 + j * 8;
        CP16(stbase + DA_VOFF + plane * DA_VPL + dv * 144 + j * 16, src);
    }
}

__global__ void __launch_bounds__(256, 1)
diffattn_mma(const float* __restrict__ subw) {
    extern __shared__ char smem[];
    const uint32_t sb = smem_u32(smem);
    const int qt = (int)gridDim.x - 1 - (int)blockIdx.x;
    const int h = blockIdx.y, b = blockIdx.z;
    const int q0 = qt * 64, kvh = h >> 1;
    const int tid = threadIdx.x, lane = tid & 31, wid = tid >> 5;
    const int wm = wid & 3, comp = wid >> 2;
    const float lam = g_lam;

#pragma unroll
    for (int i = 0; i < 8; i++) {
        int idx = tid + i * 256;
        int qc = idx >> 10, rem = idx & 1023;
        int plane = rem >> 9, r = (rem >> 3) & 63, j = idx & 7;
        const __nv_bfloat16* src = (plane ? g_ql : g_qh) +
            ((size_t)((b * S_ + q0 + r) * 32) + 2 * h + qc) * 64 + j * 8;
        CP16(sb + DA_Q + qc * DA_KC + plane * DA_KPL + r * 144 + j * 16, src);
    }
    CP_COMMIT();
    da_load_tile(sb, b, kvh, 0, tid);
    CP_COMMIT();

    const uint32_t frow = (uint32_t)(lane & 15);
    const uint32_t fkb  = (uint32_t)((lane >> 4) * 16);
    const uint32_t aqh = sb + DA_Q + comp * DA_KC + (wm * 16 + frow) * 144 + fkb;
    const uint32_t aql = aqh + DA_KPL;

    float O[16][4];
#pragma unroll
    for (int i = 0; i < 16; i++)
#pragma unroll
        for (int q = 0; q < 4; q++) O[i][q] = 0.0f;
    float mrow[2] = {-1e30f, -1e30f};
    float lrow[2] = {0.0f, 0.0f};

    int st = 0;
    for (int kt = 0; kt <= qt; kt++) {
        if (kt + 1 <= qt) {
            da_load_tile(sb + (st ^ 1) * DA_STAGE, b, kvh, (kt + 1) * 64, tid);
            CP_COMMIT();
            CP_WAIT1();
        } else {
            CP_WAIT0();
        }
        __syncthreads();

        const uint32_t stb = sb + st * DA_STAGE;
        const uint32_t kbh = stb + comp * DA_KC + frow * 144 + fkb;
        const uint32_t kbl = kbh + DA_KPL;
        const uint32_t vbh = stb + DA_VOFF + frow * 144 + fkb;
        const uint32_t vbl = vbh + DA_VPL;

        float sc[8][4];
#pragma unroll
        for (int i = 0; i < 8; i++)
#pragma unroll
            for (int q = 0; q < 4; q++) sc[i][q] = 0.0f;
#pragma unroll
        for (int kd = 0; kd < 4; kd++) {
            uint32_t ah[4], al[4];
            LDSM4(ah, aqh + kd * 32);
            LDSM4(al, aql + kd * 32);
#pragma unroll
            for (int nk = 0; nk < 4; nk++) {
                uint32_t kh4[4], kl4[4];
                LDSM4(kh4, kbh + nk * 2304 + kd * 32);
                LDSM4(kl4, kbl + nk * 2304 + kd * 32);
                uint32_t bhe[2] = {kh4[0], kh4[2]}, bho[2] = {kh4[1], kh4[3]};
                uint32_t ble[2] = {kl4[0], kl4[2]}, blo[2] = {kl4[1], kl4[3]};
                MMA16816(sc[2 * nk],     ah, bhe);
                MMA16816(sc[2 * nk],     ah, ble);
                MMA16816(sc[2 * nk],     al, bhe);
                MMA16816(sc[2 * nk + 1], ah, bho);
                MMA16816(sc[2 * nk + 1], ah, blo);
                MMA16816(sc[2 * nk + 1], al, bho);
            }
        }

        const bool diag = (kt == qt);
#pragma unroll
        for (int ri = 0; ri < 2; ri++) {
            const int row_l = wm * 16 + (lane >> 2) + ri * 8;
            float mx = -1e30f;
#pragma unroll
            for (int nt = 0; nt < 8; nt++)
#pragma unroll
                for (int j = 0; j < 2; j++) {
                    float v = sc[nt][ri * 2 + j] * SCALE_F;
                    if (diag && (nt * 8 + (lane & 3) * 2 + j > row_l)) v = -1e30f;
                    sc[nt][ri * 2 + j] = v;
                    mx = fmaxf(mx, v);
                }
            mx = fmaxf(mx, __shfl_xor_sync(0xffffffffu, mx, 1));
            mx = fmaxf(mx, __shfl_xor_sync(0xffffffffu, mx, 2));
            float mnew = fmaxf(mrow[ri], mx);
            float corr = fexp(mrow[ri] - mnew);
            mrow[ri] = mnew;
            float rs = 0.0f;
#pragma unroll
            for (int nt = 0; nt < 8; nt++)
#pragma unroll
                for (int j = 0; j < 2; j++) {
                    float p = fexp(sc[nt][ri * 2 + j] - mnew);
                    sc[nt][ri * 2 + j] = p;
                    rs += p;
                }
            rs += __shfl_xor_sync(0xffffffffu, rs, 1);
            rs += __shfl_xor_sync(0xffffffffu, rs, 2);
            lrow[ri] = lrow[ri] * corr + rs;
#pragma unroll
            for (int nt = 0; nt < 16; nt++) {
                O[nt][ri * 2]     *= corr;
                O[nt][ri * 2 + 1] *= corr;
            }
        }

#pragma unroll
        for (int kp = 0; kp < 4; kp++) {
            uint32_t ph[4], pl[4];
            cvt_pair(sc[2 * kp][0],     sc[2 * kp][1],     ph[0], pl[0]);
            cvt_pair(sc[2 * kp][2],     sc[2 * kp][3],     ph[1], pl[1]);
            cvt_pair(sc[2 * kp + 1][0], sc[2 * kp + 1][1], ph[2], pl[2]);
            cvt_pair(sc[2 * kp + 1][2], sc[2 * kp + 1][3], ph[3], pl[3]);
#pragma unroll
            for (int nt = 0; nt < 8; nt++) {
                uint32_t vh4[4], vl4[4];
                LDSM4(vh4, vbh + nt * 2304 + kp * 32);
                LDSM4(vl4, vbl + nt * 2304 + kp * 32);
                uint32_t bhe[2] = {vh4[0], vh4[2]}, bho[2] = {vh4[1], vh4[3]};
                uint32_t ble[2] = {vl4[0], vl4[2]}, blo[2] = {vl4[1], vl4[3]};
                MMA16816(O[2 * nt],     ph, bhe);
                MMA16816(O[2 * nt],     ph, ble);
                MMA16816(O[2 * nt],     pl, bhe);
                MMA16816(O[2 * nt + 1], ph, bho);
                MMA16816(O[2 * nt + 1], ph, blo);
                MMA16816(O[2 * nt + 1], pl, bho);
            }
        }
        __syncthreads();
        st ^= 1;
    }

    float* X = (float*)smem;
    const float inv0 = 1.0f / lrow[0], inv1 = 1.0f / lrow[1];
    if (comp == 1) {
#pragma unroll
        for (int ri = 0; ri < 2; ri++) {
            const int row_l = wm * 16 + (lane >> 2) + ri * 8;
            const float s = lam * (ri ? inv1 : inv0);
#pragma unroll
            for (int nt = 0; nt < 16; nt++) {
                int col = nt * 8 + (lane & 3) * 2;
                X[row_l * 130 + col]     = O[nt][ri * 2] * s;
                X[row_l * 130 + col + 1] = O[nt][ri * 2 + 1] * s;
            }
        }
    }
    __syncthreads();
    if (comp == 0) {
#pragma unroll
        for (int ri = 0; ri < 2; ri++) {
            const int row_l = wm * 16 + (lane >> 2) + ri * 8;
            const float invv = ri ? inv1 : inv0;
            float a[32];
            float ss = 0.0f;
#pragma unroll
            for (int nt = 0; nt < 16; nt++) {
                int col = nt * 8 + (lane & 3) * 2;
                float a0 = fmaf(O[nt][ri * 2],     invv, -X[row_l * 130 + col]);
                float a1 = fmaf(O[nt][ri * 2 + 1], invv, -X[row_l * 130 + col + 1]);
                a[nt * 2] = a0; a[nt * 2 + 1] = a1;
                ss = fmaf(a0, a0, ss);
                ss = fmaf(a1, a1, ss);
            }
            ss += __shfl_xor_sync(0xffffffffu, ss, 1);
            ss += __shfl_xor_sync(0xffffffffu, ss, 2);
            float rinv = rsqrtf(ss * (1.0f / 128.0f) + 1e-5f);
            float* op = g_a + (size_t)(b * S_ + q0 + row_l) * 2048 + h * 128;
#pragma unroll
            for (int nt = 0; nt < 16; nt++) {
                int col = nt * 8 + (lane & 3) * 2;
                float2 o;
                o.x = a[nt * 2]     * rinv * subw[col]     * ONE_MINUS_LI;
                o.y = a[nt * 2 + 1] * rinv * subw[col + 1] * ONE_MINUS_LI;
                *(float2*)(op + col) = o;
            }
        }
    }
}

// ---------------- launch ----------------
extern "C" void kernel_launch(void* const* d_in, const int* in_sizes, int n_in,
                              void* d_out, int out_size) {
    const float* x    = (const float*)d_in[0];
    const float* cosb = (const float*)d_in[1];
    const float* sinb = (const float*)d_in[2];
    const float* Wq   = (const float*)d_in[3];
    const float* Wk   = (const float*)d_in[4];
    const float* Wv   = (const float*)d_in[5];
    const float* Wo   = (const float*)d_in[6];
    const float* lq1  = (const float*)d_in[7];
    const float* lk1  = (const float*)d_in[8];
    const float* lq2  = (const float*)d_in[9];
    const float* lk2  = (const float*)d_in[10];
    const float* subw = (const float*)d_in[11];
    float* out = (float*)d_out;

    float *qp, *kp, *vp, *ap;
    cudaGetSymbolAddress((void**)&qp, g_q);
    cudaGetSymbolAddress((void**)&kp, g_k);
    cudaGetSymbolAddress((void**)&vp, g_v);
    cudaGetSymbolAddress((void**)&ap, g_a);
    __nv_bfloat16 *xh, *xl, *ah, *al, *wqh, *wql, *wkh, *wkl, *wvh, *wvl, *woh, *wol;
    cudaGetSymbolAddress((void**)&xh, g_xh);   cudaGetSymbolAddress((void**)&xl, g_xl);
    cudaGetSymbolAddress((void**)&ah, g_ah);   cudaGetSymbolAddress((void**)&al, g_al);
    cudaGetSymbolAddress((void**)&wqh, g_wqh); cudaGetSymbolAddress((void**)&wql, g_wql);
    cudaGetSymbolAddress((void**)&wkh, g_wkh); cudaGetSymbolAddress((void**)&wkl, g_wkl);
    cudaGetSymbolAddress((void**)&wvh, g_wvh); cudaGetSymbolAddress((void**)&wvl, g_wvl);
    cudaGetSymbolAddress((void**)&woh, g_woh); cudaGetSymbolAddress((void**)&wol, g_wol);

    cudaFuncSetAttribute(gemm_big, cudaFuncAttributeMaxDynamicSharedMemorySize, G3_SMEM);
    cudaFuncSetAttribute(gemm_kv,  cudaFuncAttributeMaxDynamicSharedMemorySize, G3_SMEM);
    cudaFuncSetAttribute(diffattn_mma, cudaFuncAttributeMaxDynamicSharedMemorySize, DA_SMEM);

    // hi/lo splits
    cvt_split<<<4096, 256>>>(x,  xh,  xl,  M_ * 2048 / 8);
    cvt_split<<<2048, 256>>>(Wq, wqh, wql, 2048 * 2048 / 8);
    cvt_split<<<1024, 256>>>(Wk, wkh, wkl, 1024 * 2048 / 8);
    cvt_split<<<1024, 256>>>(Wv, wvh, wvl, 1024 * 2048 / 8);
    cvt_split<<<2048, 256>>>(Wo, woh, wol, 2048 * 2048 / 8);
    // projections: Q full-wave, K+V merged full-wave
    gemm_big<<<dim3(8, 16), 512, G3_SMEM>>>(xh, xl, wqh, wql, qp, 2048, 2048);
    gemm_kv <<<dim3(8, 16), 512, G3_SMEM>>>(xh, xl, wkh, wkl, wvh, wvl, kp, vp, 2048);
    // attention-side preps
    prep_qk<<<(QPAIRS + KPAIRS + 255) / 256, 256>>>(cosb, sinb);
    prep_vt<<<dim3(S_ / 64, HKV_, B_), 256>>>();
    lam_kernel<<<1, 64>>>(lq1, lk1, lq2, lk2);
    // attention
    diffattn_mma<<<dim3(S_ / 64, H_, B_), 256, DA_SMEM>>>(subw);
    // output projection
    cvt_split<<<4096, 256>>>(ap, ah, al, M_ * 2048 / 8);
    gemm_big<<<dim3(8, 16), 512, G3_SMEM>>>(ah, al, woh, wol, out, 2048, 2048);
}

// round 16
// speedup vs baseline: 1.7610x; 1.7610x over previous
#include <cuda_runtime.h>
#include <cuda_bf16.h>
#include <cstdint>

// ---------------- problem constants ----------------
#define B_    2
#define S_    2048
#define E_    2048
#define H_    16
#define HKV_  8
#define D_    64
#define M_    (B_ * S_)
#define LAMBDA_INIT_F 0.78360576653f
#define ONE_MINUS_LI  0.21639423347f
#define SCALE_F       0.125f

// ---------------- scratch (device globals) ----------------
__device__ float g_q[M_ * 2048];
__device__ float g_k[M_ * 1024];
__device__ float g_v[M_ * 1024];
__device__ float g_a[M_ * 2048];
__device__ float g_lam;
__device__ __nv_bfloat16 g_xh[M_ * 2048],    g_xl[M_ * 2048];
__device__ __nv_bfloat16 g_ah[M_ * 2048],    g_al[M_ * 2048];
__device__ __nv_bfloat16 g_wqh[2048 * 2048], g_wql[2048 * 2048];
__device__ __nv_bfloat16 g_wkh[1024 * 2048], g_wkl[1024 * 2048];
__device__ __nv_bfloat16 g_wvh[1024 * 2048], g_wvl[1024 * 2048];
__device__ __nv_bfloat16 g_woh[2048 * 2048], g_wol[2048 * 2048];
__device__ __nv_bfloat16 g_qh[M_ * 2048], g_ql[M_ * 2048];
__device__ __nv_bfloat16 g_kh[M_ * 1024], g_kl[M_ * 1024];
__device__ __nv_bfloat16 g_vth[M_ * 1024], g_vtl[M_ * 1024];  // (B,HKV,2D,S)

// ---------------- helpers ----------------
__device__ __forceinline__ uint32_t smem_u32(const void* p) {
    uint32_t a;
    asm("{ .reg .u64 t; cvta.to.shared.u64 t, %1; cvt.u32.u64 %0, t; }" : "=r"(a) : "l"(p));
    return a;
}
__device__ __forceinline__ void cvt_pair(float x, float y, uint32_t& hp, uint32_t& lp) {
    __nv_bfloat16 hx = __float2bfloat16_rn(x);
    __nv_bfloat16 hy = __float2bfloat16_rn(y);
    float lx = x - __bfloat162float(hx);
    float ly = y - __bfloat162float(hy);
    hp = ((uint32_t)__bfloat16_as_ushort(hy) << 16) | (uint32_t)__bfloat16_as_ushort(hx);
    __nv_bfloat162 l2 = __floats2bfloat162_rn(lx, ly);
    lp = *reinterpret_cast<uint32_t*>(&l2);
}

#define LDSM4(r, a) \
    asm volatile("ldmatrix.sync.aligned.m8n8.x4.shared.b16 {%0,%1,%2,%3}, [%4];" \
        : "=r"((r)[0]), "=r"((r)[1]), "=r"((r)[2]), "=r"((r)[3]) : "r"(a))

#define MMA16816(c, a, b) \
    asm volatile("mma.sync.aligned.m16n8k16.row.col.f32.bf16.bf16.f32 " \
        "{%0,%1,%2,%3}, {%4,%5,%6,%7}, {%8,%9}, {%0,%1,%2,%3};" \
        : "+f"((c)[0]), "+f"((c)[1]), "+f"((c)[2]), "+f"((c)[3]) \
        : "r"((a)[0]), "r"((a)[1]), "r"((a)[2]), "r"((a)[3]), "r"((b)[0]), "r"((b)[1]))

#define CP16(dst, src) \
    asm volatile("cp.async.cg.shared.global [%0], [%1], 16;" :: "r"(dst), "l"(src))
#define CP_COMMIT() asm volatile("cp.async.commit_group;" ::: "memory")
#define CP_WAIT1()  asm volatile("cp.async.wait_group 1;" ::: "memory")
#define CP_WAIT0()  asm volatile("cp.async.wait_group 0;" ::: "memory")

// ---------------- split kernel: fp32 -> bf16 hi + bf16 lo ----------------
__global__ void __launch_bounds__(256) cvt_split(const float* __restrict__ src,
                                                 __nv_bfloat16* __restrict__ hi,
                                                 __nv_bfloat16* __restrict__ lo, int n8) {
    int i = blockIdx.x * blockDim.x + threadIdx.x;
    if (i >= n8) return;
    const float4* s = (const float4*)src + (size_t)i * 2;
    float4 v0 = s[0], v1 = s[1];
    uint32_t h[4], l[4];
    cvt_pair(v0.x, v0.y, h[0], l[0]);
    cvt_pair(v0.z, v0.w, h[1], l[1]);
    cvt_pair(v1.x, v1.y, h[2], l[2]);
    cvt_pair(v1.z, v1.w, h[3], l[3]);
    *(uint4*)(hi + (size_t)i * 8) = make_uint4(h[0], h[1], h[2], h[3]);
    *(uint4*)(lo + (size_t)i * 8) = make_uint4(l[0], l[1], l[2], l[3]);
}

// ---------------- pure-bf16 HMMA GEMM, 256x128 tile, 512 thr, cp.async 3-stage -------
// (R14-proven config: warp grid 4x4, warp tile 64x32, accum 64 regs/thread)
#define G2_APL   20480
#define G2_WPL   10240
#define G2_STAGE 61440
#define G2_NST   3
#define G2_SMEM  (G2_NST * G2_STAGE)   // 184320

__device__ __forceinline__ void g2_load(const __nv_bfloat16* __restrict__ Ah,
                                        const __nv_bfloat16* __restrict__ Al,
                                        const __nv_bfloat16* __restrict__ Wh,
                                        const __nv_bfloat16* __restrict__ Wl,
                                        int K, uint32_t sbase, int bm, int bn,
                                        int k0, int tid) {
#pragma unroll
    for (int i = 0; i < 2; i++) {
        int idx = tid + i * 512;
        int row = idx >> 2, j = idx & 3;
        uint32_t doff = (uint32_t)(row * 80 + j * 16);
        CP16(sbase + doff,          (Ah + (size_t)(bm + row) * K + k0 + j * 8));
        CP16(sbase + G2_APL + doff, (Al + (size_t)(bm + row) * K + k0 + j * 8));
    }
    {
        int row = tid >> 2, j = tid & 3;
        uint32_t doff = (uint32_t)(row * 80 + j * 16);
        CP16(sbase + 2 * G2_APL + doff,          (Wh + (size_t)(bn + row) * K + k0 + j * 8));
        CP16(sbase + 2 * G2_APL + G2_WPL + doff, (Wl + (size_t)(bn + row) * K + k0 + j * 8));
    }
}

__device__ __forceinline__ void gemm_body(
        const __nv_bfloat16* __restrict__ Ah, const __nv_bfloat16* __restrict__ Al,
        const __nv_bfloat16* __restrict__ Wh, const __nv_bfloat16* __restrict__ Wl,
        float* __restrict__ C, int N, int K, int bm, int bn) {
    extern __shared__ char smem[];
    const uint32_t sb0 = smem_u32(smem);
    const int tid = threadIdx.x, lane = tid & 31, wid = tid >> 5;
    const int wm = wid >> 2, wn = wid & 3;

    const uint32_t aoff = (uint32_t)((wm * 64 + ((lane >> 3) & 1) * 8 + (lane & 7)) * 80 +
                                     ((lane >> 4) & 1) * 16);
    const uint32_t boff = (uint32_t)((wn * 32 + ((lane >> 4) & 1) * 8 + (lane & 7)) * 80 +
                                     ((lane >> 3) & 1) * 16);

    float c[4][4][4];
#pragma unroll
    for (int i = 0; i < 4; i++)
#pragma unroll
        for (int j = 0; j < 4; j++)
#pragma unroll
            for (int q = 0; q < 4; q++) c[i][j][q] = 0.0f;

    const int nch = K >> 5;
    g2_load(Ah, Al, Wh, Wl, K, sb0, bm, bn, 0, tid);
    CP_COMMIT();
    g2_load(Ah, Al, Wh, Wl, K, sb0 + G2_STAGE, bm, bn, 32, tid);
    CP_COMMIT();

    int st = 0;
    for (int cidx = 0; cidx < nch; cidx++) {
        CP_WAIT1();
        __syncthreads();
        if (cidx + 2 < nch) {
            int st2 = st + 2; if (st2 >= G2_NST) st2 -= G2_NST;
            g2_load(Ah, Al, Wh, Wl, K, sb0 + st2 * G2_STAGE, bm, bn, (cidx + 2) << 5, tid);
        }
        CP_COMMIT();

        const uint32_t sA  = sb0 + st * G2_STAGE;
        const uint32_t sAl = sA + G2_APL;
        const uint32_t sW  = sA + 2 * G2_APL;
        const uint32_t sWl = sW + G2_WPL;
#pragma unroll
        for (int ks = 0; ks < 2; ks++) {
            uint32_t bh[4][2], bl[4][2];
#pragma unroll
            for (int p = 0; p < 2; p++) {
                uint32_t r[4];
                LDSM4(r, sW + boff + p * 1280 + ks * 32);
                bh[2 * p][0] = r[0]; bh[2 * p][1] = r[1];
                bh[2 * p + 1][0] = r[2]; bh[2 * p + 1][1] = r[3];
                LDSM4(r, sWl + boff + p * 1280 + ks * 32);
                bl[2 * p][0] = r[0]; bl[2 * p][1] = r[1];
                bl[2 * p + 1][0] = r[2]; bl[2 * p + 1][1] = r[3];
            }
#pragma unroll
            for (int mt = 0; mt < 4; mt++) {
                uint32_t ah[4], al[4];
                LDSM4(ah, sA  + aoff + mt * 1280 + ks * 32);
                LDSM4(al, sAl + aoff + mt * 1280 + ks * 32);
#pragma unroll
                for (int nt = 0; nt < 4; nt++) {
                    MMA16816(c[mt][nt], ah, bh[nt]);
                    MMA16816(c[mt][nt], ah, bl[nt]);
                    MMA16816(c[mt][nt], al, bh[nt]);
                }
            }
        }
        if (++st == G2_NST) st = 0;
    }

    const int r0 = bm + wm * 64 + (lane >> 2);
    const int c0 = bn + wn * 32 + (lane & 3) * 2;
#pragma unroll
    for (int mt = 0; mt < 4; mt++)
#pragma unroll
        for (int nt = 0; nt < 4; nt++) {
            float* p0 = C + (size_t)(r0 + mt * 16) * N + c0 + nt * 8;
            float* p1 = p0 + 8 * N;
            *(float2*)p0 = make_float2(c[mt][nt][0], c[mt][nt][1]);
            *(float2*)p1 = make_float2(c[mt][nt][2], c[mt][nt][3]);
        }
}

__global__ void __launch_bounds__(512, 1)
gemm_bfs(const __nv_bfloat16* __restrict__ Ah, const __nv_bfloat16* __restrict__ Al,
         const __nv_bfloat16* __restrict__ Wh, const __nv_bfloat16* __restrict__ Wl,
         float* __restrict__ C, int N, int K) {
    gemm_body(Ah, Al, Wh, Wl, C, N, K, blockIdx.y * 256, blockIdx.x * 128);
}

// K and V projections merged into one launch (blockIdx.x: 0-7 -> K, 8-15 -> V)
__global__ void __launch_bounds__(512, 1)
gemm_kv(const __nv_bfloat16* __restrict__ Ah, const __nv_bfloat16* __restrict__ Al,
        const __nv_bfloat16* __restrict__ Kh, const __nv_bfloat16* __restrict__ Kl,
        const __nv_bfloat16* __restrict__ Vh, const __nv_bfloat16* __restrict__ Vl,
        float* __restrict__ Ck, float* __restrict__ Cv, int K) {
    const int sel = blockIdx.x >> 3;
    const int bn = (blockIdx.x & 7) * 128;
    gemm_body(Ah, Al, sel ? Vh : Kh, sel ? Vl : Kl, sel ? Cv : Ck,
              1024, K, blockIdx.y * 256, bn);
}

// ---------------- fast exp ----------------
__device__ __forceinline__ float fexp(float x) {
    x = fmaxf(x, -80.0f);
    float y  = x * 1.44269504088896f;
    float t  = y + 12582912.0f;
    int   e  = __float_as_int(t);
    float f  = y - (t - 12582912.0f);
    float p  = 1.33335581e-3f;
    p = fmaf(p, f, 9.61812911e-3f);
    p = fmaf(p, f, 5.55041087e-2f);
    p = fmaf(p, f, 2.40226507e-1f);
    p = fmaf(p, f, 6.93147181e-1f);
    p = fmaf(p, f, 1.0f);
    return __int_as_float(__float_as_int(p) + (e << 23));
}

// ---------------- prep: rope + hi/lo split for Q,K ----------------
#define QPAIRS (M_ * 32 * 32)
#define KPAIRS (M_ * 16 * 32)
__global__ void prep_qk(const float* __restrict__ cosb, const float* __restrict__ sinb) {
    int idx = blockIdx.x * blockDim.x + threadIdx.x;
    if (idx < QPAIRS) {
        int i = idx & 31;
        int head = (idx >> 5) & 31;
        int t = idx >> 10;
        int s = t & (S_ - 1);
        float c = cosb[s * 32 + i], sn = sinb[s * 32 + i];
        const float* p = g_q + (size_t)t * 2048 + head * 64 + 2 * i;
        float x1 = p[0], x2 = p[1];
        float o1 = x1 * c - x2 * sn;
        float o2 = x1 * sn + x2 * c;
        uint32_t hp, lp;
        cvt_pair(o1, o2, hp, lp);
        size_t off = (size_t)t * 2048 + head * 64 + 2 * i;
        *(uint32_t*)(g_qh + off) = hp;
        *(uint32_t*)(g_ql + off) = lp;
    } else if (idx < QPAIRS + KPAIRS) {
        int j = idx - QPAIRS;
        int i = j & 31;
        int head = (j >> 5) & 15;
        int t = j >> 9;
        int s = t & (S_ - 1);
        float c = cosb[s * 32 + i], sn = sinb[s * 32 + i];
        const float* p = g_k + (size_t)t * 1024 + head * 64 + 2 * i;
        float x1 = p[0], x2 = p[1];
        float o1 = x1 * c - x2 * sn;
        float o2 = x1 * sn + x2 * c;
        uint32_t hp, lp;
        cvt_pair(o1, o2, hp, lp);
        size_t off = (size_t)t * 1024 + head * 64 + 2 * i;
        *(uint32_t*)(g_kh + off) = hp;
        *(uint32_t*)(g_kl + off) = lp;
    }
}

// ---------------- prep: V transpose (dv-major) + hi/lo split ----------------
__global__ void __launch_bounds__(256) prep_vt() {
    __shared__ float vt[64][132];
    const int s0 = blockIdx.x * 64, kvh = blockIdx.y, b = blockIdx.z;
    const int tid = threadIdx.x;
#pragma unroll
    for (int i = 0; i < 8; i++) {
        int idx = tid + i * 256;
        int sl = idx >> 5, dv4 = (idx & 31) * 4;
        float4 v = *(const float4*)(g_v + (size_t)((b * S_ + s0 + sl) * 8 + kvh) * 128 + dv4);
        vt[sl][dv4] = v.x; vt[sl][dv4 + 1] = v.y; vt[sl][dv4 + 2] = v.z; vt[sl][dv4 + 3] = v.w;
    }
    __syncthreads();
    const int dv = tid >> 1, half = tid & 1;
    __nv_bfloat16* oh = g_vth + (size_t)((b * 8 + kvh) * 128 + dv) * 2048 + s0 + half * 32;
    __nv_bfloat16* ol = g_vtl + (size_t)((b * 8 + kvh) * 128 + dv) * 2048 + s0 + half * 32;
#pragma unroll
    for (int g = 0; g < 4; g++) {
        uint32_t hw[4], lw[4];
#pragma unroll
        for (int e = 0; e < 4; e++) {
            float f0 = vt[half * 32 + g * 8 + 2 * e][dv];
            float f1 = vt[half * 32 + g * 8 + 2 * e + 1][dv];
            cvt_pair(f0, f1, hw[e], lw[e]);
        }
        *(uint4*)(oh + g * 8) = make_uint4(hw[0], hw[1], hw[2], hw[3]);
        *(uint4*)(ol + g * 8) = make_uint4(lw[0], lw[1], lw[2], lw[3]);
    }
}

// ---------------- lambda scalar ----------------
__global__ void lam_kernel(const float* __restrict__ lq1, const float* __restrict__ lk1,
                           const float* __restrict__ lq2, const float* __restrict__ lk2) {
    __shared__ float s1a[2], s2a[2];
    int t = threadIdx.x;
    float p1 = lq1[t] * lk1[t];
    float p2 = lq2[t] * lk2[t];
#pragma unroll
    for (int o = 16; o > 0; o >>= 1) {
        p1 += __shfl_xor_sync(0xffffffffu, p1, o);
        p2 += __shfl_xor_sync(0xffffffffu, p2, o);
    }
    if ((t & 31) == 0) { s1a[t >> 5] = p1; s2a[t >> 5] = p2; }
    __syncthreads();
    if (t == 0)
        g_lam = expf(s1a[0] + s1a[1]) - expf(s2a[0] + s2a[1]) + LAMBDA_INIT_F;
}

// ---------------- HMMA dual-component flash attention, cp.async double-buffered ------
#define DA_KPL   9216
#define DA_KC    18432
#define DA_VPL   18432
#define DA_VOFF  36864
#define DA_STAGE 73728
#define DA_Q     147456
#define DA_SMEM  184320

__device__ __forceinline__ void da_load_tile(uint32_t stbase, int b, int kvh, int k0, int tid) {
#pragma unroll
    for (int i = 0; i < 8; i++) {
        int idx = tid + i * 256;
        int comp = idx >> 10, rem = idx & 1023;
        int plane = rem >> 9, r = (rem >> 3) & 63, j = idx & 7;
        const __nv_bfloat16* src = (plane ? g_kl : g_kh) +
            ((size_t)((b * S_ + k0 + r) * 16) + 2 * kvh + comp) * 64 + j * 8;
        CP16(stbase + comp * DA_KC + plane * DA_KPL + r * 144 + j * 16, src);
    }
#pragma unroll
    for (int i = 0; i < 8; i++) {
        int idx = tid + i * 256;
        int plane = idx >> 10, rem = idx & 1023;
        int dv = rem >> 3, j = idx & 7;
        const __nv_bfloat16* src = (plane ? g_vtl : g_vth) +
            (size_t)((b * 8 + kvh) * 128 + dv) * 2048 + k0 + j * 8;
        CP16(stbase + DA_VOFF + plane * DA_VPL + dv * 144 + j * 16, src);
    }
}

__global__ void __launch_bounds__(256, 1)
diffattn_mma(const float* __restrict__ subw) {
    extern __shared__ char smem[];
    const uint32_t sb = smem_u32(smem);
    const int qt = (int)gridDim.x - 1 - (int)blockIdx.x;
    const int h = blockIdx.y, b = blockIdx.z;
    const int q0 = qt * 64, kvh = h >> 1;
    const int tid = threadIdx.x, lane = tid & 31, wid = tid >> 5;
    const int wm = wid & 3, comp = wid >> 2;
    const float lam = g_lam;

#pragma unroll
    for (int i = 0; i < 8; i++) {
        int idx = tid + i * 256;
        int qc = idx >> 10, rem = idx & 1023;
        int plane = rem >> 9, r = (rem >> 3) & 63, j = idx & 7;
        const __nv_bfloat16* src = (plane ? g_ql : g_qh) +
            ((size_t)((b * S_ + q0 + r) * 32) + 2 * h + qc) * 64 + j * 8;
        CP16(sb + DA_Q + qc * DA_KC + plane * DA_KPL + r * 144 + j * 16, src);
    }
    CP_COMMIT();
    da_load_tile(sb, b, kvh, 0, tid);
    CP_COMMIT();

    const uint32_t frow = (uint32_t)(lane & 15);
    const uint32_t fkb  = (uint32_t)((lane >> 4) * 16);
    const uint32_t aqh = sb + DA_Q + comp * DA_KC + (wm * 16 + frow) * 144 + fkb;
    const uint32_t aql = aqh + DA_KPL;

    float O[16][4];
#pragma unroll
    for (int i = 0; i < 16; i++)
#pragma unroll
        for (int q = 0; q < 4; q++) O[i][q] = 0.0f;
    float mrow[2] = {-1e30f, -1e30f};
    float lrow[2] = {0.0f, 0.0f};

    int st = 0;
    for (int kt = 0; kt <= qt; kt++) {
        if (kt + 1 <= qt) {
            da_load_tile(sb + (st ^ 1) * DA_STAGE, b, kvh, (kt + 1) * 64, tid);
            CP_COMMIT();
            CP_WAIT1();
        } else {
            CP_WAIT0();
        }
        __syncthreads();

        const uint32_t stb = sb + st * DA_STAGE;
        const uint32_t kbh = stb + comp * DA_KC + frow * 144 + fkb;
        const uint32_t kbl = kbh + DA_KPL;
        const uint32_t vbh = stb + DA_VOFF + frow * 144 + fkb;
        const uint32_t vbl = vbh + DA_VPL;

        float sc[8][4];
#pragma unroll
        for (int i = 0; i < 8; i++)
#pragma unroll
            for (int q = 0; q < 4; q++) sc[i][q] = 0.0f;
#pragma unroll
        for (int kd = 0; kd < 4; kd++) {
            uint32_t ah[4], al[4];
            LDSM4(ah, aqh + kd * 32);
            LDSM4(al, aql + kd * 32);
#pragma unroll
            for (int nk = 0; nk < 4; nk++) {
                uint32_t kh4[4], kl4[4];
                LDSM4(kh4, kbh + nk * 2304 + kd * 32);
                LDSM4(kl4, kbl + nk * 2304 + kd * 32);
                uint32_t bhe[2] = {kh4[0], kh4[2]}, bho[2] = {kh4[1], kh4[3]};
                uint32_t ble[2] = {kl4[0], kl4[2]}, blo[2] = {kl4[1], kl4[3]};
                MMA16816(sc[2 * nk],     ah, bhe);
                MMA16816(sc[2 * nk],     ah, ble);
                MMA16816(sc[2 * nk],     al, bhe);
                MMA16816(sc[2 * nk + 1], ah, bho);
                MMA16816(sc[2 * nk + 1], ah, blo);
                MMA16816(sc[2 * nk + 1], al, bho);
            }
        }

        const bool diag = (kt == qt);
#pragma unroll
        for (int ri = 0; ri < 2; ri++) {
            const int row_l = wm * 16 + (lane >> 2) + ri * 8;
            float mx = -1e30f;
#pragma unroll
            for (int nt = 0; nt < 8; nt++)
#pragma unroll
                for (int j = 0; j < 2; j++) {
                    float v = sc[nt][ri * 2 + j] * SCALE_F;
                    if (diag && (nt * 8 + (lane & 3) * 2 + j > row_l)) v = -1e30f;
                    sc[nt][ri * 2 + j] = v;
                    mx = fmaxf(mx, v);
                }
            mx = fmaxf(mx, __shfl_xor_sync(0xffffffffu, mx, 1));
            mx = fmaxf(mx, __shfl_xor_sync(0xffffffffu, mx, 2));
            float mnew = fmaxf(mrow[ri], mx);
            float corr = fexp(mrow[ri] - mnew);
            mrow[ri] = mnew;
            float rs = 0.0f;
#pragma unroll
            for (int nt = 0; nt < 8; nt++)
#pragma unroll
                for (int j = 0; j < 2; j++) {
                    float p = fexp(sc[nt][ri * 2 + j] - mnew);
                    sc[nt][ri * 2 + j] = p;
                    rs += p;
                }
            rs += __shfl_xor_sync(0xffffffffu, rs, 1);
            rs += __shfl_xor_sync(0xffffffffu, rs, 2);
            lrow[ri] = lrow[ri] * corr + rs;
#pragma unroll
            for (int nt = 0; nt < 16; nt++) {
                O[nt][ri * 2]     *= corr;
                O[nt][ri * 2 + 1] *= corr;
            }
        }

#pragma unroll
        for (int kp = 0; kp < 4; kp++) {
            uint32_t ph[4], pl[4];
            cvt_pair(sc[2 * kp][0],     sc[2 * kp][1],     ph[0], pl[0]);
            cvt_pair(sc[2 * kp][2],     sc[2 * kp][3],     ph[1], pl[1]);
            cvt_pair(sc[2 * kp + 1][0], sc[2 * kp + 1][1], ph[2], pl[2]);
            cvt_pair(sc[2 * kp + 1][2], sc[2 * kp + 1][3], ph[3], pl[3]);
#pragma unroll
            for (int nt = 0; nt < 8; nt++) {
                uint32_t vh4[4], vl4[4];
                LDSM4(vh4, vbh + nt * 2304 + kp * 32);
                LDSM4(vl4, vbl + nt * 2304 + kp * 32);
                uint32_t bhe[2] = {vh4[0], vh4[2]}, bho[2] = {vh4[1], vh4[3]};
                uint32_t ble[2] = {vl4[0], vl4[2]}, blo[2] = {vl4[1], vl4[3]};
                MMA16816(O[2 * nt],     ph, bhe);
                MMA16816(O[2 * nt],     ph, ble);
                MMA16816(O[2 * nt],     pl, bhe);
                MMA16816(O[2 * nt + 1], ph, bho);
                MMA16816(O[2 * nt + 1], ph, blo);
                MMA16816(O[2 * nt + 1], pl, bho);
            }
        }
        __syncthreads();
        st ^= 1;
    }

    float* X = (float*)smem;
    const float inv0 = 1.0f / lrow[0], inv1 = 1.0f / lrow[1];
    if (comp == 1) {
#pragma unroll
        for (int ri = 0; ri < 2; ri++) {
            const int row_l = wm * 16 + (lane >> 2) + ri * 8;
            const float s = lam * (ri ? inv1 : inv0);
#pragma unroll
            for (int nt = 0; nt < 16; nt++) {
                int col = nt * 8 + (lane & 3) * 2;
                X[row_l * 130 + col]     = O[nt][ri * 2] * s;
                X[row_l * 130 + col + 1] = O[nt][ri * 2 + 1] * s;
            }
        }
    }
    __syncthreads();
    if (comp == 0) {
#pragma unroll
        for (int ri = 0; ri < 2; ri++) {
            const int row_l = wm * 16 + (lane >> 2) + ri * 8;
            const float invv = ri ? inv1 : inv0;
            float a[32];
            float ss = 0.0f;
#pragma unroll
            for (int nt = 0; nt < 16; nt++) {
                int col = nt * 8 + (lane & 3) * 2;
                float a0 = fmaf(O[nt][ri * 2],     invv, -X[row_l * 130 + col]);
                float a1 = fmaf(O[nt][ri * 2 + 1], invv, -X[row_l * 130 + col + 1]);
                a[nt * 2] = a0; a[nt * 2 + 1] = a1;
                ss = fmaf(a0, a0, ss);
                ss = fmaf(a1, a1, ss);
            }
            ss += __shfl_xor_sync(0xffffffffu, ss, 1);
            ss += __shfl_xor_sync(0xffffffffu, ss, 2);
            float rinv = rsqrtf(ss * (1.0f / 128.0f) + 1e-5f);
            float* op = g_a + (size_t)(b * S_ + q0 + row_l) * 2048 + h * 128;
#pragma unroll
            for (int nt = 0; nt < 16; nt++) {
                int col = nt * 8 + (lane & 3) * 2;
                float2 o;
                o.x = a[nt * 2]     * rinv * subw[col]     * ONE_MINUS_LI;
                o.y = a[nt * 2 + 1] * rinv * subw[col + 1] * ONE_MINUS_LI;
                *(float2*)(op + col) = o;
            }
        }
    }
}

// ---------------- launch ----------------
extern "C" void kernel_launch(void* const* d_in, const int* in_sizes, int n_in,
                              void* d_out, int out_size) {
    const float* x    = (const float*)d_in[0];
    const float* cosb = (const float*)d_in[1];
    const float* sinb = (const float*)d_in[2];
    const float* Wq   = (const float*)d_in[3];
    const float* Wk   = (const float*)d_in[4];
    const float* Wv   = (const float*)d_in[5];
    const float* Wo   = (const float*)d_in[6];
    const float* lq1  = (const float*)d_in[7];
    const float* lk1  = (const float*)d_in[8];
    const float* lq2  = (const float*)d_in[9];
    const float* lk2  = (const float*)d_in[10];
    const float* subw = (const float*)d_in[11];
    float* out = (float*)d_out;

    float *qp, *kp, *vp, *ap;
    cudaGetSymbolAddress((void**)&qp, g_q);
    cudaGetSymbolAddress((void**)&kp, g_k);
    cudaGetSymbolAddress((void**)&vp, g_v);
    cudaGetSymbolAddress((void**)&ap, g_a);
    __nv_bfloat16 *xh, *xl, *ah, *al, *wqh, *wql, *wkh, *wkl, *wvh, *wvl, *woh, *wol;
    cudaGetSymbolAddress((void**)&xh, g_xh);   cudaGetSymbolAddress((void**)&xl, g_xl);
    cudaGetSymbolAddress((void**)&ah, g_ah);   cudaGetSymbolAddress((void**)&al, g_al);
    cudaGetSymbolAddress((void**)&wqh, g_wqh); cudaGetSymbolAddress((void**)&wql, g_wql);
    cudaGetSymbolAddress((void**)&wkh, g_wkh); cudaGetSymbolAddress((void**)&wkl, g_wkl);
    cudaGetSymbolAddress((void**)&wvh, g_wvh); cudaGetSymbolAddress((void**)&wvl, g_wvl);
    cudaGetSymbolAddress((void**)&woh, g_woh); cudaGetSymbolAddress((void**)&wol, g_wol);

    cudaFuncSetAttribute(gemm_bfs, cudaFuncAttributeMaxDynamicSharedMemorySize, G2_SMEM);
    cudaFuncSetAttribute(gemm_kv,  cudaFuncAttributeMaxDynamicSharedMemorySize, G2_SMEM);
    cudaFuncSetAttribute(diffattn_mma, cudaFuncAttributeMaxDynamicSharedMemorySize, DA_SMEM);

    // hi/lo splits
    cvt_split<<<4096, 256>>>(x,  xh,  xl,  M_ * 2048 / 8);
    cvt_split<<<2048, 256>>>(Wq, wqh, wql, 2048 * 2048 / 8);
    cvt_split<<<1024, 256>>>(Wk, wkh, wkl, 1024 * 2048 / 8);
    cvt_split<<<1024, 256>>>(Wv, wvh, wvl, 1024 * 2048 / 8);
    cvt_split<<<2048, 256>>>(Wo, woh, wol, 2048 * 2048 / 8);
    // projections: Q (256 CTAs), K+V merged (256 CTAs)
    gemm_bfs<<<dim3(16, 16), 512, G2_SMEM>>>(xh, xl, wqh, wql, qp, 2048, 2048);
    gemm_kv <<<dim3(16, 16), 512, G2_SMEM>>>(xh, xl, wkh, wkl, wvh, wvl, kp, vp, 2048);
    // attention-side preps
    prep_qk<<<(QPAIRS + KPAIRS + 255) / 256, 256>>>(cosb, sinb);
    prep_vt<<<dim3(S_ / 64, HKV_, B_), 256>>>();
    lam_kernel<<<1, 64>>>(lq1, lk1, lq2, lk2);
    // attention
    diffattn_mma<<<dim3(S_ / 64, H_, B_), 256, DA_SMEM>>>(subw);
    // output projection
    cvt_split<<<4096, 256>>>(ap, ah, al, M_ * 2048 / 8);
    gemm_bfs<<<dim3(16, 16), 512, G2_SMEM>>>(ah, al, woh, wol, out, 2048, 2048);
}